// round 12
// baseline (speedup 1.0000x reference)
#include <cuda_runtime.h>
#include <cuda_bf16.h>
#include <mma.h>
#include <math.h>

using namespace nvcuda;

#define NHEAD 12
#define NKV   3
#define HD    64
#define TSEQ  2048
#define BATCH 2
#define NE    768
#define NKVD  (NKV*HD)         // 192
#define MTOT  (BATCH*TSEQ)     // 4096
#define WINDOW 1024

// fp32 scratch
__device__ float g_Q[MTOT * NHEAD * HD];   // (b,t,h,d)
__device__ float g_K[MTOT * NKV  * HD];
__device__ float g_V[MTOT * NKV  * HD];
__device__ float g_A[MTOT * NHEAD * HD];   // attention out

// bf16 hi/lo split copies (x = hi + lo, lo*lo term dropped => ~2^-18 rel err)
__device__ __nv_bfloat16 cXh[MTOT * NE],  cXl[MTOT * NE];
__device__ __nv_bfloat16 cAh[MTOT * NE],  cAl[MTOT * NE];
__device__ __nv_bfloat16 cWqh[NE * NE],   cWql[NE * NE];
__device__ __nv_bfloat16 cWkh[NKVD * NE], cWkl[NKVD * NE];
__device__ __nv_bfloat16 cWvh[NKVD * NE], cWvl[NKVD * NE];
__device__ __nv_bfloat16 cWoh[NE * NE],   cWol[NE * NE];

// ---------------------------------------------------------------------------
// float -> (bf16 hi, bf16 lo).  srcSel: 0 = ext src, 1 = g_A.
// dSel: 0 cX, 1 cWq, 2 cWk, 3 cWv, 4 cWo, 5 cA.
// ---------------------------------------------------------------------------
__global__ void cvt_split(const float* __restrict__ src, int srcSel, int n,
                          int dSel) {
    const float* s = srcSel ? (const float*)g_A : src;
    __nv_bfloat16 *h, *l;
    switch (dSel) {
        case 0: h = cXh;  l = cXl;  break;
        case 1: h = cWqh; l = cWql; break;
        case 2: h = cWkh; l = cWkl; break;
        case 3: h = cWvh; l = cWvl; break;
        case 4: h = cWoh; l = cWol; break;
        default: h = cAh; l = cAl;  break;
    }
    int i = blockIdx.x * blockDim.x + threadIdx.x;
    if (i < n) {
        float x = s[i];
        __nv_bfloat16 hb = __float2bfloat16(x);
        float r = x - __bfloat162float(hb);
        h[i] = hb;
        l[i] = __float2bfloat16(r);
    }
}

// ---------------------------------------------------------------------------
// Split-bf16 tensor-core GEMM:  C[M,N] = A[M,768] * B[N,768]^T  (fp32 out)
// BM=128, BN=64, BK=16. 128 threads = 4 warps; each warp 32x64 (2x4 wmma
// m16n16k16 tiles). Per k-step, 3 mma per tile: Ah*Bh + Ah*Bl + Al*Bh.
// aSel: 0 cX, 1 cA.  bSel: 0 Wq, 1 Wk, 2 Wv, 3 Wo.
// cSel: 0 g_Q, 1 g_K, 2 g_V, 3 Cext.
// ---------------------------------------------------------------------------
#define BM 128
#define BN 64
#define BK 16
#define SPAD 24    // smem row stride (multiple of 8 for ldm)

__global__ void __launch_bounds__(128) bgemm(int aSel, int bSel,
                                             float* __restrict__ Cext,
                                             int cSel, int N) {
    const __nv_bfloat16* Ah = aSel ? cAh : cXh;
    const __nv_bfloat16* Al = aSel ? cAl : cXl;
    const __nv_bfloat16 *Bh, *Bl;
    switch (bSel) {
        case 0: Bh = cWqh; Bl = cWql; break;
        case 1: Bh = cWkh; Bl = cWkl; break;
        case 2: Bh = cWvh; Bl = cWvl; break;
        default: Bh = cWoh; Bl = cWol; break;
    }
    float* C;
    switch (cSel) {
        case 0: C = g_Q; break;
        case 1: C = g_K; break;
        case 2: C = g_V; break;
        default: C = Cext; break;
    }

    __shared__ __nv_bfloat16 sAh[BM][SPAD], sAl[BM][SPAD];
    __shared__ __nv_bfloat16 sBh[BN][SPAD], sBl[BN][SPAD];

    const int bm = blockIdx.y * BM;
    const int bn = blockIdx.x * BN;
    const int tid = threadIdx.x;
    const int warp = tid >> 5;

    wmma::fragment<wmma::accumulator, 16, 16, 16, float> acc[2][4];
#pragma unroll
    for (int mt = 0; mt < 2; mt++)
#pragma unroll
        for (int nt = 0; nt < 4; nt++) wmma::fill_fragment(acc[mt][nt], 0.f);

    for (int k0 = 0; k0 < NE; k0 += BK) {
        // A tile: 128 rows, each thread owns one row (hi + lo, 16 bf16 each)
        {
            const __nv_bfloat16* gh = Ah + (size_t)(bm + tid) * NE + k0;
            const __nv_bfloat16* gl = Al + (size_t)(bm + tid) * NE + k0;
            *(uint4*)&sAh[tid][0] = *(const uint4*)gh;
            *(uint4*)&sAh[tid][8] = *((const uint4*)gh + 1);
            *(uint4*)&sAl[tid][0] = *(const uint4*)gl;
            *(uint4*)&sAl[tid][8] = *((const uint4*)gl + 1);
        }
        // B tile: 64 rows; threads 0-63 load hi, 64-127 load lo
        {
            int br = tid & 63;
            const __nv_bfloat16* gb =
                ((tid < 64) ? Bh : Bl) + (size_t)(bn + br) * NE + k0;
            __nv_bfloat16(*sB)[SPAD] = (tid < 64) ? sBh : sBl;
            *(uint4*)&sB[br][0] = *(const uint4*)gb;
            *(uint4*)&sB[br][8] = *((const uint4*)gb + 1);
        }
        __syncthreads();

        wmma::fragment<wmma::matrix_a, 16, 16, 16, __nv_bfloat16,
                       wmma::row_major> ah[2], al[2];
        wmma::fragment<wmma::matrix_b, 16, 16, 16, __nv_bfloat16,
                       wmma::col_major> bh[4], bl[4];
#pragma unroll
        for (int mt = 0; mt < 2; mt++) {
            wmma::load_matrix_sync(ah[mt], &sAh[warp * 32 + mt * 16][0], SPAD);
            wmma::load_matrix_sync(al[mt], &sAl[warp * 32 + mt * 16][0], SPAD);
        }
#pragma unroll
        for (int nt = 0; nt < 4; nt++) {
            wmma::load_matrix_sync(bh[nt], &sBh[nt * 16][0], SPAD);
            wmma::load_matrix_sync(bl[nt], &sBl[nt * 16][0], SPAD);
        }
#pragma unroll
        for (int mt = 0; mt < 2; mt++)
#pragma unroll
            for (int nt = 0; nt < 4; nt++) {
                wmma::mma_sync(acc[mt][nt], ah[mt], bh[nt], acc[mt][nt]);
                wmma::mma_sync(acc[mt][nt], ah[mt], bl[nt], acc[mt][nt]);
                wmma::mma_sync(acc[mt][nt], al[mt], bh[nt], acc[mt][nt]);
            }
        __syncthreads();
    }

#pragma unroll
    for (int mt = 0; mt < 2; mt++)
#pragma unroll
        for (int nt = 0; nt < 4; nt++) {
            int row = bm + warp * 32 + mt * 16;
            int col = bn + nt * 16;
            wmma::store_matrix_sync(&C[(size_t)row * N + col], acc[mt][nt], N,
                                    wmma::mem_row_major);
        }
}

// ---------------------------------------------------------------------------
// RoPE (negated rotation — validated round 10), in place on g_Q / g_K.
// ---------------------------------------------------------------------------
__global__ void rope_kernel() {
    const int bt = blockIdx.x;
    const int head = threadIdx.x >> 5;    // 0..14
    const int lane = threadIdx.x & 31;
    const float t = (float)(bt & (TSEQ - 1));

    float* ptr;
    if (head < NHEAD) ptr = g_Q + ((size_t)bt * NHEAD + head) * HD;
    else              ptr = g_K + ((size_t)bt * NKV + (head - NHEAD)) * HD;

    float inv = powf(10000.f, -(float)lane / 32.f);
    float ang = t * inv;
    float c, s;
    sincosf(ang, &c, &s);
    float x1 = ptr[lane];
    float x2 = ptr[lane + 32];
    ptr[lane]      = x1 * c + x2 * s;     // rotation by -ang
    ptr[lane + 32] = x2 * c - x1 * s;
}

// ---------------------------------------------------------------------------
// Sliding-window attention (fp32, one-pass softmax; validated round 10/11).
// ---------------------------------------------------------------------------
#define ATTN_SMEM ((64*68*3 + 64*64 + 16*4*17) * 4)   // 72960 bytes

__global__ void __launch_bounds__(256) attn_kernel() {
    extern __shared__ float sm[];
    float* Qs   = sm;               // [64][68]
    float* Ks   = Qs + 64 * 68;     // [64][68]
    float* Ps   = Ks + 64 * 68;     // [64][68]  key-major
    float* Vs   = Ps + 64 * 68;     // [64][64]
    float* Lred = Vs + 64 * 64;     // [64][17]

    const int b = blockIdx.z;
    const int h = blockIdx.y;
    const int q0 = blockIdx.x * 64;
    const int kvh = h >> 2;
    const int tid = threadIdx.x;
    const int ty = tid >> 4;
    const int tx = tid & 15;
    const float SCALE = 0.21650635094610965f;   // (64*4/12)^-0.5

    for (int i = tid; i < 64 * 64; i += 256) {
        int q = i >> 6, d = i & 63;
        Qs[q * 68 + d] =
            g_Q[((size_t)(b * TSEQ + q0 + q) * NHEAD + h) * HD + d] * SCALE;
    }

    float acc[4][4];
    float lpart[4];
    int st[4];
#pragma unroll
    for (int qi = 0; qi < 4; qi++) {
        lpart[qi] = 0.f;
        int qg = q0 + ty * 4 + qi;
        st[qi] = min(max(qg - WINDOW / 2, 0), TSEQ - WINDOW);
#pragma unroll
        for (int di = 0; di < 4; di++) acc[qi][di] = 0.f;
    }

    const int smin = min(max(q0 - WINDOW / 2, 0), TSEQ - WINDOW);
    const int smax = min(max(q0 + 63 - WINDOW / 2, 0), TSEQ - WINDOW);
    const int jend = smax + WINDOW;

    for (int jt = smin; jt < jend; jt += 64) {
        __syncthreads();
        for (int i = tid; i < 64 * 64; i += 256) {
            int j = i >> 6, d = i & 63;
            size_t base = ((size_t)(b * TSEQ + jt + j) * NKV + kvh) * HD + d;
            Ks[j * 68 + d] = g_K[base];
            Vs[j * 64 + d] = g_V[base];
        }
        __syncthreads();

        float s[4][4];
#pragma unroll
        for (int qi = 0; qi < 4; qi++)
#pragma unroll
            for (int ki = 0; ki < 4; ki++) s[qi][ki] = 0.f;

#pragma unroll
        for (int d = 0; d < 64; d += 4) {
            float4 qv[4], kv[4];
#pragma unroll
            for (int qi = 0; qi < 4; qi++)
                qv[qi] = *(const float4*)&Qs[(ty * 4 + qi) * 68 + d];
#pragma unroll
            for (int ki = 0; ki < 4; ki++)
                kv[ki] = *(const float4*)&Ks[(tx * 4 + ki) * 68 + d];
#pragma unroll
            for (int qi = 0; qi < 4; qi++)
#pragma unroll
                for (int ki = 0; ki < 4; ki++)
                    s[qi][ki] += qv[qi].x * kv[ki].x + qv[qi].y * kv[ki].y +
                                 qv[qi].z * kv[ki].z + qv[qi].w * kv[ki].w;
        }

#pragma unroll
        for (int ki = 0; ki < 4; ki++) {
            int jg = jt + tx * 4 + ki;
#pragma unroll
            for (int qi = 0; qi < 4; qi++) {
                bool valid = (jg >= st[qi]) && (jg < st[qi] + WINDOW);
                float e = valid ? __expf(s[qi][ki]) : 0.f;
                lpart[qi] += e;
                Ps[(tx * 4 + ki) * 68 + ty * 4 + qi] = e;
            }
        }
        __syncthreads();

#pragma unroll 8
        for (int j = 0; j < 64; j++) {
            float4 pj = *(const float4*)&Ps[j * 68 + ty * 4];
            float4 vj = *(const float4*)&Vs[j * 64 + tx * 4];
            acc[0][0] += pj.x * vj.x; acc[0][1] += pj.x * vj.y;
            acc[0][2] += pj.x * vj.z; acc[0][3] += pj.x * vj.w;
            acc[1][0] += pj.y * vj.x; acc[1][1] += pj.y * vj.y;
            acc[1][2] += pj.y * vj.z; acc[1][3] += pj.y * vj.w;
            acc[2][0] += pj.z * vj.x; acc[2][1] += pj.z * vj.y;
            acc[2][2] += pj.z * vj.z; acc[2][3] += pj.z * vj.w;
            acc[3][0] += pj.w * vj.x; acc[3][1] += pj.w * vj.y;
            acc[3][2] += pj.w * vj.z; acc[3][3] += pj.w * vj.w;
        }
    }

    __syncthreads();
#pragma unroll
    for (int qi = 0; qi < 4; qi++)
        Lred[(ty * 4 + qi) * 17 + tx] = lpart[qi];
    __syncthreads();

#pragma unroll
    for (int qi = 0; qi < 4; qi++) {
        float l = 0.f;
#pragma unroll
        for (int t2 = 0; t2 < 16; t2++) l += Lred[(ty * 4 + qi) * 17 + t2];
        float inv = 1.f / l;
        int q = q0 + ty * 4 + qi;
        float4 o = make_float4(acc[qi][0] * inv, acc[qi][1] * inv,
                               acc[qi][2] * inv, acc[qi][3] * inv);
        *(float4*)&g_A[((size_t)(b * TSEQ + q) * NHEAD + h) * HD + tx * 4] = o;
    }
}

// ---------------------------------------------------------------------------
extern "C" void kernel_launch(void* const* d_in, const int* in_sizes, int n_in,
                              void* d_out, int out_size) {
    // Input-order defense (dict vs alphabetical metadata order).
    const float *X, *Wq, *Wk, *Wv, *Wo;
    if (in_sizes[0] == MTOT * NE) {                 // dict insertion order
        X  = (const float*)d_in[0];
        Wq = (const float*)d_in[1];
        Wk = (const float*)d_in[2];
        Wv = (const float*)d_in[3];
        Wo = (const float*)d_in[4];
    } else {                                        // alphabetical order
        Wk = (const float*)d_in[0];
        Wo = (const float*)d_in[1];
        Wq = (const float*)d_in[2];
        Wv = (const float*)d_in[3];
        X  = (const float*)d_in[4];
    }
    float* out = (float*)d_out;

    // split conversions
    cvt_split<<<(MTOT * NE + 255) / 256, 256>>>(X, 0, MTOT * NE, 0);
    cvt_split<<<(NE * NE + 255) / 256, 256>>>(Wq, 0, NE * NE, 1);
    cvt_split<<<(NKVD * NE + 255) / 256, 256>>>(Wk, 0, NKVD * NE, 2);
    cvt_split<<<(NKVD * NE + 255) / 256, 256>>>(Wv, 0, NKVD * NE, 3);
    cvt_split<<<(NE * NE + 255) / 256, 256>>>(Wo, 0, NE * NE, 4);

    // projections on tensor cores
    bgemm<<<dim3(NE / BN, MTOT / BM), 128>>>(0, 0, nullptr, 0, NE);     // Q
    bgemm<<<dim3(NKVD / BN, MTOT / BM), 128>>>(0, 1, nullptr, 1, NKVD); // K
    bgemm<<<dim3(NKVD / BN, MTOT / BM), 128>>>(0, 2, nullptr, 2, NKVD); // V

    rope_kernel<<<MTOT, 480>>>();

    static int smem_set = 0;
    if (!smem_set) {
        cudaFuncSetAttribute(attn_kernel,
                             cudaFuncAttributeMaxDynamicSharedMemorySize,
                             ATTN_SMEM);
        smem_set = 1;
    }
    attn_kernel<<<dim3(TSEQ / 64, NHEAD, BATCH), 256, ATTN_SMEM>>>();

    // output projection
    cvt_split<<<(MTOT * NE + 255) / 256, 256>>>(nullptr, 1, MTOT * NE, 5);
    bgemm<<<dim3(NE / BN, MTOT / BM), 128>>>(1, 3, out, 3, NE);
}

// round 16
// speedup vs baseline: 1.6986x; 1.6986x over previous
#include <cuda_runtime.h>
#include <cuda_bf16.h>
#include <stdint.h>
#include <cstdint>
#include <math.h>

#define NHEAD 12
#define NKV   3
#define HD    64
#define TSEQ  2048
#define BATCH 2
#define NE    768
#define NKVD  (NKV*HD)         // 192
#define MTOT  (BATCH*TSEQ)     // 4096
#define WINDOW 1024

// fp32 scratch
__device__ float g_Q[MTOT * NHEAD * HD];
__device__ float g_K[MTOT * NKV  * HD];
__device__ float g_V[MTOT * NKV  * HD];
__device__ float g_A[MTOT * NHEAD * HD];

// bf16 hi/lo split copies (x = hi + lo; lo*lo dropped => ~2^-18 rel err)
__device__ __align__(16) __nv_bfloat16 cXh[MTOT * NE],  cXl[MTOT * NE];
__device__ __align__(16) __nv_bfloat16 cAh[MTOT * NE],  cAl[MTOT * NE];
__device__ __align__(16) __nv_bfloat16 cWqh[NE * NE],   cWql[NE * NE];
__device__ __align__(16) __nv_bfloat16 cWkh[NKVD * NE], cWkl[NKVD * NE];
__device__ __align__(16) __nv_bfloat16 cWvh[NKVD * NE], cWvl[NKVD * NE];
__device__ __align__(16) __nv_bfloat16 cWoh[NE * NE],   cWol[NE * NE];

__device__ __forceinline__ uint32_t smem_u32(const void* p) {
    return (uint32_t)__cvta_generic_to_shared(p);
}

// ---------------------------------------------------------------------------
// float -> (bf16 hi, bf16 lo).  srcSel: 0 ext, 1 g_A.
// dSel: 0 cX, 1 cWq, 2 cWk, 3 cWv, 4 cWo, 5 cA.
// ---------------------------------------------------------------------------
__global__ void cvt_split(const float* __restrict__ src, int srcSel, int n,
                          int dSel) {
    const float* s = srcSel ? (const float*)g_A : src;
    __nv_bfloat16 *h, *l;
    switch (dSel) {
        case 0: h = cXh;  l = cXl;  break;
        case 1: h = cWqh; l = cWql; break;
        case 2: h = cWkh; l = cWkl; break;
        case 3: h = cWvh; l = cWvl; break;
        case 4: h = cWoh; l = cWol; break;
        default: h = cAh; l = cAl;  break;
    }
    int i = blockIdx.x * blockDim.x + threadIdx.x;
    if (i < n) {
        float x = s[i];
        __nv_bfloat16 hb = __float2bfloat16(x);
        h[i] = hb;
        l[i] = __float2bfloat16(x - __bfloat162float(hb));
    }
}

// ---------------------------------------------------------------------------
// mma.sync bf16 split GEMM:  C[M,N] = A[M,768]*B[N,768]^T, fp32 out.
// 256 thr / 8 warps; BM=128, BN=64, BK=16; warp tile 32x32 = 2(m16) x 4(n8).
// Fragment mapping (PTX m16n8k16.row.col):
//  A frag (4 regs): lane g=l/4,t4=l%4: a0=A[g][2t4,2t4+1] a1=A[g+8][..]
//                   a2=A[g][2t4+8..] a3=A[g+8][2t4+8..]
//  loaded by ldmatrix.x4: lanes l: mi=l/8, rr=l%8: rows (mi&1)*8+rr,
//  col (mi>>1)*8 -> regs {r0..r3}={a0..a3}.
//  B frag (2 regs/tile): b0={B[2t4][g],B[2t4+1][g]}, b1={B[2t4+8][g],..}
//  with B[k][n]=W[n][k]; ldmatrix.x4 over [n16][k16] chunk of W gives
//  {tile0.b0, tile1.b0, tile0.b1, tile1.b1}.
// ---------------------------------------------------------------------------
#define ASTR 24   // smem row stride in bf16 (48B: conflict-free ldmatrix)

__device__ __forceinline__ void ldm_x4(uint32_t& r0, uint32_t& r1,
                                       uint32_t& r2, uint32_t& r3,
                                       uint32_t addr) {
    asm volatile("ldmatrix.sync.aligned.m8n8.x4.shared.b16 {%0,%1,%2,%3}, [%4];"
                 : "=r"(r0), "=r"(r1), "=r"(r2), "=r"(r3) : "r"(addr));
}
__device__ __forceinline__ void mma16816(float* d, const uint32_t* a,
                                         uint32_t b0, uint32_t b1) {
    asm volatile(
        "mma.sync.aligned.m16n8k16.row.col.f32.bf16.bf16.f32 "
        "{%0,%1,%2,%3}, {%4,%5,%6,%7}, {%8,%9}, {%0,%1,%2,%3};"
        : "+f"(d[0]), "+f"(d[1]), "+f"(d[2]), "+f"(d[3])
        : "r"(a[0]), "r"(a[1]), "r"(a[2]), "r"(a[3]), "r"(b0), "r"(b1));
}

__global__ void __launch_bounds__(256) mma_gemm(int aSel, int bSel,
                                                float* __restrict__ Cext,
                                                int cSel, int N) {
    const __nv_bfloat16* Ah = aSel ? cAh : cXh;
    const __nv_bfloat16* Al = aSel ? cAl : cXl;
    const __nv_bfloat16 *Bh, *Bl;
    switch (bSel) {
        case 0: Bh = cWqh; Bl = cWql; break;
        case 1: Bh = cWkh; Bl = cWkl; break;
        case 2: Bh = cWvh; Bl = cWvl; break;
        default: Bh = cWoh; Bl = cWol; break;
    }
    float* C;
    switch (cSel) {
        case 0: C = g_Q; break;
        case 1: C = g_K; break;
        case 2: C = g_V; break;
        default: C = Cext; break;
    }

    __shared__ __align__(16) __nv_bfloat16 sAh[128 * ASTR], sAl[128 * ASTR];
    __shared__ __align__(16) __nv_bfloat16 sBh[64 * ASTR],  sBl[64 * ASTR];

    const int tid = threadIdx.x;
    const int lane = tid & 31;
    const int wid = tid >> 5;
    const int wr = wid & 3;        // warp row (32 M-rows each)
    const int wc = wid >> 2;       // warp col (32 N-cols each)
    const int bm = blockIdx.y * 128;
    const int bn = blockIdx.x * 64;

    float acc[2][4][4];
#pragma unroll
    for (int mt = 0; mt < 2; mt++)
#pragma unroll
        for (int nt = 0; nt < 4; nt++)
#pragma unroll
            for (int r = 0; r < 4; r++) acc[mt][nt][r] = 0.f;

    // ldmatrix lane addresses
    const int mi = lane >> 3, rr = lane & 7;
    uint32_t aAddrH[2], aAddrL[2], bAddrH[2], bAddrL[2];
#pragma unroll
    for (int mt = 0; mt < 2; mt++) {
        int row = wr * 32 + mt * 16 + (mi & 1) * 8 + rr;
        uint32_t off = (uint32_t)(row * ASTR + (mi >> 1) * 8) * 2;
        aAddrH[mt] = smem_u32(sAh) + off;
        aAddrL[mt] = smem_u32(sAl) + off;
    }
#pragma unroll
    for (int np = 0; np < 2; np++) {
        int row = wc * 32 + np * 16 + (mi & 1) * 8 + rr;
        uint32_t off = (uint32_t)(row * ASTR + (mi >> 1) * 8) * 2;
        bAddrH[np] = smem_u32(sBh) + off;
        bAddrL[np] = smem_u32(sBl) + off;
    }

    const int lrow = tid >> 1;
    const int lhalf = (tid & 1) * 8;

    for (int k0 = 0; k0 < NE; k0 += 16) {
        __syncthreads();
        // A tile 128x16 (hi+lo)
        {
            size_t g = (size_t)(bm + lrow) * NE + k0 + lhalf;
            *(uint4*)&sAh[lrow * ASTR + lhalf] = *(const uint4*)(Ah + g);
            *(uint4*)&sAl[lrow * ASTR + lhalf] = *(const uint4*)(Al + g);
        }
        // B tile 64x16 (hi+lo)
        if (tid < 128) {
            int brow = tid >> 1;
            int bhalf = (tid & 1) * 8;
            size_t g = (size_t)(bn + brow) * NE + k0 + bhalf;
            *(uint4*)&sBh[brow * ASTR + bhalf] = *(const uint4*)(Bh + g);
            *(uint4*)&sBl[brow * ASTR + bhalf] = *(const uint4*)(Bl + g);
        }
        __syncthreads();

        uint32_t ah[2][4], al[2][4], bh[2][4], bl[2][4];
#pragma unroll
        for (int mt = 0; mt < 2; mt++) {
            ldm_x4(ah[mt][0], ah[mt][1], ah[mt][2], ah[mt][3], aAddrH[mt]);
            ldm_x4(al[mt][0], al[mt][1], al[mt][2], al[mt][3], aAddrL[mt]);
        }
#pragma unroll
        for (int np = 0; np < 2; np++) {
            ldm_x4(bh[np][0], bh[np][1], bh[np][2], bh[np][3], bAddrH[np]);
            ldm_x4(bl[np][0], bl[np][1], bl[np][2], bl[np][3], bAddrL[np]);
        }
#pragma unroll
        for (int mt = 0; mt < 2; mt++)
#pragma unroll
            for (int np = 0; np < 2; np++) {
                // tile nt=2np:   b0=reg0, b1=reg2 ; tile 2np+1: reg1, reg3
                mma16816(acc[mt][2 * np], ah[mt], bh[np][0], bh[np][2]);
                mma16816(acc[mt][2 * np], ah[mt], bl[np][0], bl[np][2]);
                mma16816(acc[mt][2 * np], al[mt], bh[np][0], bh[np][2]);
                mma16816(acc[mt][2 * np + 1], ah[mt], bh[np][1], bh[np][3]);
                mma16816(acc[mt][2 * np + 1], ah[mt], bl[np][1], bl[np][3]);
                mma16816(acc[mt][2 * np + 1], al[mt], bh[np][1], bh[np][3]);
            }
    }

    // writeback: d0,d1 -> (row g, col 2t4..+1); d2,d3 -> row g+8
    const int g = lane >> 2, t4 = lane & 3;
#pragma unroll
    for (int mt = 0; mt < 2; mt++)
#pragma unroll
        for (int nt = 0; nt < 4; nt++) {
            int row = bm + wr * 32 + mt * 16 + g;
            int col = bn + wc * 32 + nt * 8 + t4 * 2;
            *(float2*)&C[(size_t)row * N + col] =
                make_float2(acc[mt][nt][0], acc[mt][nt][1]);
            *(float2*)&C[(size_t)(row + 8) * N + col] =
                make_float2(acc[mt][nt][2], acc[mt][nt][3]);
        }
}

// ---------------------------------------------------------------------------
// RoPE (negated rotation — validated round 10), in place on g_Q / g_K.
// ---------------------------------------------------------------------------
__global__ void rope_kernel() {
    const int bt = blockIdx.x;
    const int head = threadIdx.x >> 5;
    const int lane = threadIdx.x & 31;
    const float t = (float)(bt & (TSEQ - 1));

    float* ptr;
    if (head < NHEAD) ptr = g_Q + ((size_t)bt * NHEAD + head) * HD;
    else              ptr = g_K + ((size_t)bt * NKV + (head - NHEAD)) * HD;

    float inv = powf(10000.f, -(float)lane / 32.f);
    float ang = t * inv;
    float c, s;
    sincosf(ang, &c, &s);
    float x1 = ptr[lane];
    float x2 = ptr[lane + 32];
    ptr[lane]      = x1 * c + x2 * s;
    ptr[lane + 32] = x2 * c - x1 * s;
}

// ---------------------------------------------------------------------------
// Fast exp on FMA/ALU pipes (no MUFU): exp(x) = 2^(x*log2e), float-magic
// rint, deg-6 Taylor of 2^f on f in [-1/2,1/2] (|rel err| < 1e-7).
// Valid for |x| < ~80 (scores here are |x| <~ 3).
// ---------------------------------------------------------------------------
__device__ __forceinline__ float fast_exp(float x) {
    float y = x * 1.4426950408889634f;
    float z = y + 12582912.0f;            // 2^23 * 1.5
    float nf = z - 12582912.0f;
    float f = y - nf;
    int sc = (__float_as_int(z) + 127) << 23;
    float p = 1.5403530e-4f;
    p = fmaf(p, f, 1.3333558e-3f);
    p = fmaf(p, f, 9.6181291e-3f);
    p = fmaf(p, f, 5.5504109e-2f);
    p = fmaf(p, f, 2.4022651e-1f);
    p = fmaf(p, f, 6.9314718e-1f);
    p = fmaf(p, f, 1.0f);
    return __int_as_float(sc) * p;
}

// ---------------------------------------------------------------------------
// Sliding-window attention (fp32, one-pass softmax; validated rounds 10-12).
// Only change: __expf -> fast_exp (MUFU -> FMA pipe).
// ---------------------------------------------------------------------------
#define ATTN_SMEM ((64*68*3 + 64*64 + 16*4*17) * 4)   // 72960 bytes

__global__ void __launch_bounds__(256) attn_kernel() {
    extern __shared__ float sm[];
    float* Qs   = sm;
    float* Ks   = Qs + 64 * 68;
    float* Ps   = Ks + 64 * 68;
    float* Vs   = Ps + 64 * 68;
    float* Lred = Vs + 64 * 64;

    const int b = blockIdx.z;
    const int h = blockIdx.y;
    const int q0 = blockIdx.x * 64;
    const int kvh = h >> 2;
    const int tid = threadIdx.x;
    const int ty = tid >> 4;
    const int tx = tid & 15;
    const float SCALE = 0.21650635094610965f;

    for (int i = tid; i < 64 * 64; i += 256) {
        int q = i >> 6, d = i & 63;
        Qs[q * 68 + d] =
            g_Q[((size_t)(b * TSEQ + q0 + q) * NHEAD + h) * HD + d] * SCALE;
    }

    float acc[4][4];
    float lpart[4];
    int st[4];
#pragma unroll
    for (int qi = 0; qi < 4; qi++) {
        lpart[qi] = 0.f;
        int qg = q0 + ty * 4 + qi;
        st[qi] = min(max(qg - WINDOW / 2, 0), TSEQ - WINDOW);
#pragma unroll
        for (int di = 0; di < 4; di++) acc[qi][di] = 0.f;
    }

    const int smin = min(max(q0 - WINDOW / 2, 0), TSEQ - WINDOW);
    const int smax = min(max(q0 + 63 - WINDOW / 2, 0), TSEQ - WINDOW);
    const int jend = smax + WINDOW;

    for (int jt = smin; jt < jend; jt += 64) {
        __syncthreads();
        for (int i = tid; i < 64 * 64; i += 256) {
            int j = i >> 6, d = i & 63;
            size_t base = ((size_t)(b * TSEQ + jt + j) * NKV + kvh) * HD + d;
            Ks[j * 68 + d] = g_K[base];
            Vs[j * 64 + d] = g_V[base];
        }
        __syncthreads();

        float s[4][4];
#pragma unroll
        for (int qi = 0; qi < 4; qi++)
#pragma unroll
            for (int ki = 0; ki < 4; ki++) s[qi][ki] = 0.f;

#pragma unroll
        for (int d = 0; d < 64; d += 4) {
            float4 qv[4], kv[4];
#pragma unroll
            for (int qi = 0; qi < 4; qi++)
                qv[qi] = *(const float4*)&Qs[(ty * 4 + qi) * 68 + d];
#pragma unroll
            for (int ki = 0; ki < 4; ki++)
                kv[ki] = *(const float4*)&Ks[(tx * 4 + ki) * 68 + d];
#pragma unroll
            for (int qi = 0; qi < 4; qi++)
#pragma unroll
                for (int ki = 0; ki < 4; ki++)
                    s[qi][ki] += qv[qi].x * kv[ki].x + qv[qi].y * kv[ki].y +
                                 qv[qi].z * kv[ki].z + qv[qi].w * kv[ki].w;
        }

#pragma unroll
        for (int ki = 0; ki < 4; ki++) {
            int jg = jt + tx * 4 + ki;
#pragma unroll
            for (int qi = 0; qi < 4; qi++) {
                bool valid = (jg >= st[qi]) && (jg < st[qi] + WINDOW);
                float e = valid ? fast_exp(s[qi][ki]) : 0.f;
                lpart[qi] += e;
                Ps[(tx * 4 + ki) * 68 + ty * 4 + qi] = e;
            }
        }
        __syncthreads();

#pragma unroll 8
        for (int j = 0; j < 64; j++) {
            float4 pj = *(const float4*)&Ps[j * 68 + ty * 4];
            float4 vj = *(const float4*)&Vs[j * 64 + tx * 4];
            acc[0][0] += pj.x * vj.x; acc[0][1] += pj.x * vj.y;
            acc[0][2] += pj.x * vj.z; acc[0][3] += pj.x * vj.w;
            acc[1][0] += pj.y * vj.x; acc[1][1] += pj.y * vj.y;
            acc[1][2] += pj.y * vj.z; acc[1][3] += pj.y * vj.w;
            acc[2][0] += pj.z * vj.x; acc[2][1] += pj.z * vj.y;
            acc[2][2] += pj.z * vj.z; acc[2][3] += pj.z * vj.w;
            acc[3][0] += pj.w * vj.x; acc[3][1] += pj.w * vj.y;
            acc[3][2] += pj.w * vj.z; acc[3][3] += pj.w * vj.w;
        }
    }

    __syncthreads();
#pragma unroll
    for (int qi = 0; qi < 4; qi++)
        Lred[(ty * 4 + qi) * 17 + tx] = lpart[qi];
    __syncthreads();

#pragma unroll
    for (int qi = 0; qi < 4; qi++) {
        float l = 0.f;
#pragma unroll
        for (int t2 = 0; t2 < 16; t2++) l += Lred[(ty * 4 + qi) * 17 + t2];
        float inv = 1.f / l;
        int q = q0 + ty * 4 + qi;
        float4 o = make_float4(acc[qi][0] * inv, acc[qi][1] * inv,
                               acc[qi][2] * inv, acc[qi][3] * inv);
        *(float4*)&g_A[((size_t)(b * TSEQ + q) * NHEAD + h) * HD + tx * 4] = o;
    }
}

// ---------------------------------------------------------------------------
extern "C" void kernel_launch(void* const* d_in, const int* in_sizes, int n_in,
                              void* d_out, int out_size) {
    const float *X, *Wq, *Wk, *Wv, *Wo;
    if (in_sizes[0] == MTOT * NE) {                 // dict insertion order
        X  = (const float*)d_in[0];
        Wq = (const float*)d_in[1];
        Wk = (const float*)d_in[2];
        Wv = (const float*)d_in[3];
        Wo = (const float*)d_in[4];
    } else {                                        // alphabetical order
        Wk = (const float*)d_in[0];
        Wo = (const float*)d_in[1];
        Wq = (const float*)d_in[2];
        Wv = (const float*)d_in[3];
        X  = (const float*)d_in[4];
    }
    float* out = (float*)d_out;

    static int attr_set = 0;
    if (!attr_set) {
        cudaFuncSetAttribute(attn_kernel,
                             cudaFuncAttributeMaxDynamicSharedMemorySize,
                             ATTN_SMEM);
        attr_set = 1;
    }

    cvt_split<<<(MTOT * NE + 255) / 256, 256>>>(X, 0, MTOT * NE, 0);
    cvt_split<<<(NE * NE + 255) / 256, 256>>>(Wq, 0, NE * NE, 1);
    cvt_split<<<(NKVD * NE + 255) / 256, 256>>>(Wk, 0, NKVD * NE, 2);
    cvt_split<<<(NKVD * NE + 255) / 256, 256>>>(Wv, 0, NKVD * NE, 3);
    cvt_split<<<(NE * NE + 255) / 256, 256>>>(Wo, 0, NE * NE, 4);

    mma_gemm<<<dim3(NE / 64, MTOT / 128), 256>>>(0, 0, nullptr, 0, NE);
    mma_gemm<<<dim3(NKVD / 64, MTOT / 128), 256>>>(0, 1, nullptr, 1, NKVD);
    mma_gemm<<<dim3(NKVD / 64, MTOT / 128), 256>>>(0, 2, nullptr, 2, NKVD);

    rope_kernel<<<MTOT, 480>>>();

    attn_kernel<<<dim3(TSEQ / 64, NHEAD, BATCH), 256, ATTN_SMEM>>>();

    cvt_split<<<(MTOT * NE + 255) / 256, 256>>>(nullptr, 1, MTOT * NE, 5);
    mma_gemm<<<dim3(NE / 64, MTOT / 128), 256>>>(1, 3, out, 3, NE);
}